// round 1
// baseline (speedup 1.0000x reference)
#include <cuda_runtime.h>

#define H 128
#define MAXP 25000
#define RB 16

// Scratch for parent aggregation (allocations are forbidden; use device global).
__device__ __align__(256) float g_agg[MAXP * H];

// Phase 1: out = prop_z (full copy), g_agg = 0
__global__ void k_init(const float4* __restrict__ src, float4* __restrict__ dst,
                       int n4_copy, int n4_zero) {
    int i = blockIdx.x * blockDim.x + threadIdx.x;
    if (i < n4_copy) dst[i] = src[i];
    if (i < n4_zero) reinterpret_cast<float4*>(g_agg)[i] = make_float4(0.f, 0.f, 0.f, 0.f);
}

// Phase 2: one warp per edge. Parent edges: g_agg[dst] += prop_z[src].
// Sibling edges: out[dst] += mol_z[src] (dst < n_prop by construction).
// Each lane moves 16B via vector red.global.add.v4.f32.
__global__ void k_scatter(const float* __restrict__ prop_z, const float* __restrict__ mol_z,
                          const int* __restrict__ psrc, const int* __restrict__ pdst,
                          const int* __restrict__ ssrc, const int* __restrict__ sdst,
                          float* __restrict__ out, int ep, int es) {
    int gw = (blockIdx.x * blockDim.x + threadIdx.x) >> 5;
    int lane = threadIdx.x & 31;
    const float* sb;
    float* db;
    int s, d;
    if (gw < ep) {
        s = psrc[gw]; d = pdst[gw];
        sb = prop_z;  db = g_agg;
    } else {
        int e = gw - ep;
        if (e >= es) return;
        s = ssrc[e]; d = sdst[e];
        sb = mol_z;  db = out;
    }
    float4 v = reinterpret_cast<const float4*>(sb + (size_t)s * H)[lane];
    float* p = db + (size_t)d * H + lane * 4;
    asm volatile("red.global.add.v4.f32 [%0], {%1,%2,%3,%4};"
                 :: "l"(p), "f"(v.x), "f"(v.y), "f"(v.z), "f"(v.w)
                 : "memory");
}

// Phase 3: out[r] += relu(g_agg[r] @ W^T + b) for r < n_prop.
// Block: 128 threads (one output column each), RB=16 rows per block.
// W staged transposed in smem with 129-stride padding -> conflict-free reads.
__global__ void k_gemm(const float* __restrict__ W, const float* __restrict__ bias,
                       float* __restrict__ out, int n_prop) {
    __shared__ float Wt[64 * 129];   // k-tile of 64, Wt[k][c] = W[c][kt+k]
    __shared__ float As[RB * H];
    int c = threadIdx.x;             // 0..127
    int row0 = blockIdx.x * RB;

    for (int i = threadIdx.x; i < RB * H; i += H) {
        int rr = row0 + (i >> 7);
        As[i] = (rr < n_prop) ? g_agg[rr * H + (i & 127)] : 0.f;
    }

    float acc[RB];
#pragma unroll
    for (int r = 0; r < RB; r++) acc[r] = 0.f;

    for (int kt = 0; kt < H; kt += 64) {
        __syncthreads();
        // Coalesced gmem read, conflict-free smem write (129-pad).
        for (int i = threadIdx.x; i < 64 * H; i += H) {
            int cc = i >> 6;
            int kk = i & 63;
            Wt[kk * 129 + cc] = W[cc * H + kt + kk];
        }
        __syncthreads();
#pragma unroll
        for (int k = 0; k < 64; k++) {
            float w = Wt[k * 129 + c];
#pragma unroll
            for (int r = 0; r < RB; r++)
                acc[r] += As[r * H + kt + k] * w;
        }
    }

    float bb = bias[c];
#pragma unroll
    for (int r = 0; r < RB; r++) {
        int rr = row0 + r;
        if (rr < n_prop) {
            float u = acc[r] + bb;
            out[rr * H + c] += fmaxf(u, 0.f);
        }
    }
}

extern "C" void kernel_launch(void* const* d_in, const int* in_sizes, int n_in,
                              void* d_out, int out_size) {
    const float* prop_z = (const float*)d_in[0];
    const float* mol_z  = (const float*)d_in[1];
    const float* W      = (const float*)d_in[2];
    const float* b      = (const float*)d_in[3];
    const int* psrc = (const int*)d_in[4];
    const int* pdst = (const int*)d_in[5];
    const int* ssrc = (const int*)d_in[6];
    const int* sdst = (const int*)d_in[7];

    int n_nodes = in_sizes[0] / H;
    int ep      = in_sizes[4];
    int es      = in_sizes[6];
    int n_prop  = in_sizes[8];
    float* out  = (float*)d_out;

    int n4_copy = n_nodes * (H / 4);
    int n4_zero = n_prop * (H / 4);
    int n4 = n4_copy > n4_zero ? n4_copy : n4_zero;
    k_init<<<(n4 + 255) / 256, 256>>>((const float4*)prop_z, (float4*)out,
                                      n4_copy, n4_zero);

    long long total_threads = ((long long)ep + es) * 32;
    int blocks = (int)((total_threads + 255) / 256);
    k_scatter<<<blocks, 256>>>(prop_z, mol_z, psrc, pdst, ssrc, sdst, out, ep, es);

    k_gemm<<<(n_prop + RB - 1) / RB, H>>>(W, b, out, n_prop);
}

// round 2
// speedup vs baseline: 1.3832x; 1.3832x over previous
#include <cuda_runtime.h>

#define H 128
#define MAXP 25000
#define MAXE 600000
#define RB 16

// Device-global scratch (allocations forbidden).
__device__ __align__(256) float g_agg[MAXP * H];      // parent aggregation result
__device__ int g_pcnt[MAXP], g_scnt[MAXP];            // degree histograms
__device__ int g_poff[MAXP + 1], g_soff[MAXP + 1];    // CSR offsets
__device__ int g_pcur[MAXP], g_scur[MAXP];            // fill cursors
__device__ int g_pesrc[MAXE], g_sesrc[MAXE];          // CSR edge src lists
__device__ int g_bsum[64], g_coff[64];                // scan block sums / chunk offsets

// ---------------------------------------------------------------------------
// Phase 1: out = prop_z (full copy), zero histograms
__global__ void k_init(const float4* __restrict__ src, float4* __restrict__ dst,
                       int n4_copy, int n_prop) {
    int i = blockIdx.x * blockDim.x + threadIdx.x;
    if (i < n4_copy) dst[i] = src[i];
    if (i < n_prop) { g_pcnt[i] = 0; g_scnt[i] = 0; }
}

// Phase 2a: degree histogram for both edge sets
__global__ void k_hist(const int* __restrict__ pdst, const int* __restrict__ sdst,
                       int ep, int es) {
    int i = blockIdx.x * blockDim.x + threadIdx.x;
    if (i < ep) atomicAdd(&g_pcnt[pdst[i]], 1);
    else {
        int j = i - ep;
        if (j < es) atomicAdd(&g_scnt[sdst[j]], 1);
    }
}

// Phase 2b: exclusive scan (3 passes). Chunk = 1024, grid.y selects array.
__global__ void k_scan1(int n) {
    const int* src = blockIdx.y ? g_scnt : g_pcnt;
    int i = blockIdx.x * 1024 + threadIdx.x;
    int v = (i < n) ? src[i] : 0;
#pragma unroll
    for (int o = 16; o; o >>= 1) v += __shfl_down_sync(0xFFFFFFFFu, v, o);
    __shared__ int ws[32];
    if ((threadIdx.x & 31) == 0) ws[threadIdx.x >> 5] = v;
    __syncthreads();
    if (threadIdx.x < 32) {
        int t = ws[threadIdx.x];
#pragma unroll
        for (int o = 16; o; o >>= 1) t += __shfl_down_sync(0xFFFFFFFFu, t, o);
        if (threadIdx.x == 0) g_bsum[blockIdx.y * 32 + blockIdx.x] = t;
    }
}

__global__ void k_scan2(int nchunks) {
    int y = threadIdx.x;        // launched with 2 threads
    if (y < 2) {
        int run = 0;
        for (int c = 0; c < nchunks; c++) {
            g_coff[y * 32 + c] = run;
            run += g_bsum[y * 32 + c];
        }
    }
}

__global__ void k_scan3(int n) {
    const int* src = blockIdx.y ? g_scnt : g_pcnt;
    int* off = blockIdx.y ? g_soff : g_poff;
    int* cur = blockIdx.y ? g_scur : g_pcur;
    int i = blockIdx.x * 1024 + threadIdx.x;
    int v = (i < n) ? src[i] : 0;
    int lane = threadIdx.x & 31, w = threadIdx.x >> 5;
    int x = v;
#pragma unroll
    for (int o = 1; o < 32; o <<= 1) {
        int t = __shfl_up_sync(0xFFFFFFFFu, x, o);
        if (lane >= o) x += t;
    }
    __shared__ int ws[32];
    if (lane == 31) ws[w] = x;
    __syncthreads();
    if (w == 0) {
        int t = ws[lane];
#pragma unroll
        for (int o = 1; o < 32; o <<= 1) {
            int u = __shfl_up_sync(0xFFFFFFFFu, t, o);
            if (lane >= o) t += u;
        }
        ws[lane] = t;
    }
    __syncthreads();
    int excl = x - v + (w ? ws[w - 1] : 0) + g_coff[blockIdx.y * 32 + blockIdx.x];
    if (i < n) { off[i] = excl; cur[i] = excl; }
    if (i == n - 1) off[n] = excl + v;
}

// Phase 2c: fill CSR edge lists
__global__ void k_fill(const int* __restrict__ psrc, const int* __restrict__ pdst,
                       const int* __restrict__ ssrc, const int* __restrict__ sdst,
                       int ep, int es) {
    int i = blockIdx.x * blockDim.x + threadIdx.x;
    if (i < ep) {
        int d = pdst[i];
        int p = atomicAdd(&g_pcur[d], 1);
        g_pesrc[p] = psrc[i];
    } else {
        int j = i - ep;
        if (j < es) {
            int d = sdst[j];
            int p = atomicAdd(&g_scur[d], 1);
            g_sesrc[p] = ssrc[j];
        }
    }
}

// Phase 3: gather-sum. One warp per (dst row, edge set). No atomics.
__global__ void k_gather(const float* __restrict__ prop_z, const float* __restrict__ mol_z,
                         float* __restrict__ out, int n_prop) {
    int gw = (blockIdx.x * blockDim.x + threadIdx.x) >> 5;
    int lane = threadIdx.x & 31;
    bool sib = gw >= n_prop;
    int d = sib ? gw - n_prop : gw;
    if (d >= n_prop) return;
    const int* off = sib ? g_soff : g_poff;
    const int* esrc = sib ? g_sesrc : g_pesrc;
    const float* src = sib ? mol_z : prop_z;

    int beg = off[d], end = off[d + 1];
    float4 acc = make_float4(0.f, 0.f, 0.f, 0.f);
    int e = beg;
    for (; e + 4 <= end; e += 4) {
        int s0 = esrc[e], s1 = esrc[e + 1], s2 = esrc[e + 2], s3 = esrc[e + 3];
        float4 a = __ldg(reinterpret_cast<const float4*>(src + (size_t)s0 * H) + lane);
        float4 b = __ldg(reinterpret_cast<const float4*>(src + (size_t)s1 * H) + lane);
        float4 c = __ldg(reinterpret_cast<const float4*>(src + (size_t)s2 * H) + lane);
        float4 f = __ldg(reinterpret_cast<const float4*>(src + (size_t)s3 * H) + lane);
        acc.x += (a.x + b.x) + (c.x + f.x);
        acc.y += (a.y + b.y) + (c.y + f.y);
        acc.z += (a.z + b.z) + (c.z + f.z);
        acc.w += (a.w + b.w) + (c.w + f.w);
    }
    for (; e < end; e++) {
        int s = esrc[e];
        float4 a = __ldg(reinterpret_cast<const float4*>(src + (size_t)s * H) + lane);
        acc.x += a.x; acc.y += a.y; acc.z += a.z; acc.w += a.w;
    }

    if (sib) {
        float4* o = reinterpret_cast<float4*>(out + (size_t)d * H) + lane;
        float4 v = *o;
        v.x += acc.x; v.y += acc.y; v.z += acc.z; v.w += acc.w;
        *o = v;
    } else {
        reinterpret_cast<float4*>(g_agg + (size_t)d * H)[lane] = acc;
    }
}

// Phase 4: out[r] += relu(g_agg[r] @ W^T + b) for r < n_prop.
__global__ void k_gemm(const float* __restrict__ W, const float* __restrict__ bias,
                       float* __restrict__ out, int n_prop) {
    __shared__ float Wt[64 * 129];   // Wt[k][c] = W[c][kt+k], 129-pad
    __shared__ float As[RB * H];
    int c = threadIdx.x;             // 0..127
    int row0 = blockIdx.x * RB;

    for (int i = threadIdx.x; i < RB * H; i += H) {
        int rr = row0 + (i >> 7);
        As[i] = (rr < n_prop) ? g_agg[rr * H + (i & 127)] : 0.f;
    }

    float acc[RB];
#pragma unroll
    for (int r = 0; r < RB; r++) acc[r] = 0.f;

    for (int kt = 0; kt < H; kt += 64) {
        __syncthreads();
        for (int i = threadIdx.x; i < 64 * H; i += H) {
            int cc = i >> 6;
            int kk = i & 63;
            Wt[kk * 129 + cc] = W[cc * H + kt + kk];
        }
        __syncthreads();
#pragma unroll
        for (int k = 0; k < 64; k++) {
            float w = Wt[k * 129 + c];
#pragma unroll
            for (int r = 0; r < RB; r++)
                acc[r] += As[r * H + kt + k] * w;
        }
    }

    float bb = bias[c];
#pragma unroll
    for (int r = 0; r < RB; r++) {
        int rr = row0 + r;
        if (rr < n_prop) {
            float u = acc[r] + bb;
            out[rr * H + c] += fmaxf(u, 0.f);
        }
    }
}

extern "C" void kernel_launch(void* const* d_in, const int* in_sizes, int n_in,
                              void* d_out, int out_size) {
    const float* prop_z = (const float*)d_in[0];
    const float* mol_z  = (const float*)d_in[1];
    const float* W      = (const float*)d_in[2];
    const float* b      = (const float*)d_in[3];
    const int* psrc = (const int*)d_in[4];
    const int* pdst = (const int*)d_in[5];
    const int* ssrc = (const int*)d_in[6];
    const int* sdst = (const int*)d_in[7];

    int n_nodes = in_sizes[0] / H;
    int ep      = in_sizes[4];
    int es      = in_sizes[6];
    int n_prop  = in_sizes[8];
    float* out  = (float*)d_out;

    int n4_copy = n_nodes * (H / 4);
    int init_n = n4_copy > n_prop ? n4_copy : n_prop;
    k_init<<<(init_n + 255) / 256, 256>>>((const float4*)prop_z, (float4*)out,
                                          n4_copy, n_prop);

    int ne = ep + es;
    k_hist<<<(ne + 255) / 256, 256>>>(pdst, sdst, ep, es);

    int nchunks = (n_prop + 1023) / 1024;
    dim3 sg(nchunks, 2);
    k_scan1<<<sg, 1024>>>(n_prop);
    k_scan2<<<1, 2>>>(nchunks);
    k_scan3<<<sg, 1024>>>(n_prop);

    k_fill<<<(ne + 255) / 256, 256>>>(psrc, pdst, ssrc, sdst, ep, es);

    long long gw = (long long)2 * n_prop * 32;
    k_gather<<<(int)((gw + 255) / 256), 256>>>(prop_z, mol_z, out, n_prop);

    k_gemm<<<(n_prop + RB - 1) / RB, H>>>(W, b, out, n_prop);
}

// round 3
// speedup vs baseline: 1.4006x; 1.0126x over previous
#include <cuda_runtime.h>

#define H 128
#define MAXP 25000
#define MAXE 600000
#define BM 64
#define BK 32

// Device-global scratch (allocations forbidden). Zero-initialized at load;
// g_pcnt/g_scnt are re-zeroed by k_scan after use so every replay starts clean.
__device__ __align__(256) float g_agg[MAXP * H];
__device__ int g_pcnt[MAXP], g_scnt[MAXP];
__device__ int g_poff[MAXP + 1], g_soff[MAXP + 1];
__device__ int g_pcur[MAXP], g_scur[MAXP];
__device__ int g_pesrc[MAXE], g_sesrc[MAXE];

// ---------------------------------------------------------------------------
// Phase 1: copy rows [n_prop, n_nodes) of prop_z -> out, and degree histogram.
__global__ void k_pre(const float4* __restrict__ src, float4* __restrict__ dst,
                      int off4, int n4copy,
                      const int* __restrict__ pdst, const int* __restrict__ sdst,
                      int ep, int es) {
    int i = blockIdx.x * blockDim.x + threadIdx.x;
    if (i < n4copy) dst[off4 + i] = src[off4 + i];
    if (i < ep) atomicAdd(&g_pcnt[pdst[i]], 1);
    else {
        int j = i - ep;
        if (j < es) atomicAdd(&g_scnt[sdst[j]], 1);
    }
}

// ---------------------------------------------------------------------------
// Phase 2: single-kernel exclusive scan. grid=2 (one block per edge set),
// 1024 threads, 25 contiguous elements per thread. Zeroes cnt after reading.
__global__ void k_scan(int n) {
    int* cnt = blockIdx.x ? g_scnt : g_pcnt;
    int* off = blockIdx.x ? g_soff : g_poff;
    int* cur = blockIdx.x ? g_scur : g_pcur;
    const int PER = 25;                 // covers n <= 25600
    int t = threadIdx.x;
    int base = t * PER;
    int loc[PER];
    int sum = 0;
#pragma unroll
    for (int j = 0; j < PER; j++) {
        int idx = base + j;
        int v = (idx < n) ? cnt[idx] : 0;
        loc[j] = sum;
        sum += v;
    }
    // block exclusive scan of per-thread sums
    int lane = t & 31, w = t >> 5;
    int x = sum;
#pragma unroll
    for (int o = 1; o < 32; o <<= 1) {
        int u = __shfl_up_sync(0xFFFFFFFFu, x, o);
        if (lane >= o) x += u;
    }
    __shared__ int ws[32];
    if (lane == 31) ws[w] = x;
    __syncthreads();
    if (w == 0) {
        int tt = ws[lane];
#pragma unroll
        for (int o = 1; o < 32; o <<= 1) {
            int u = __shfl_up_sync(0xFFFFFFFFu, tt, o);
            if (lane >= o) tt += u;
        }
        ws[lane] = tt;
    }
    __syncthreads();
    int excl = x - sum + (w ? ws[w - 1] : 0);
#pragma unroll
    for (int j = 0; j < PER; j++) {
        int idx = base + j;
        if (idx < n) {
            int o = excl + loc[j];
            off[idx] = o;
            cur[idx] = o;
            cnt[idx] = 0;               // reset for next replay
        }
    }
    if (t == 1023) off[n] = excl + sum;
}

// ---------------------------------------------------------------------------
// Phase 3: fill CSR edge lists via cursor atomics.
__global__ void k_fill(const int* __restrict__ psrc, const int* __restrict__ pdst,
                       const int* __restrict__ ssrc, const int* __restrict__ sdst,
                       int ep, int es) {
    int i = blockIdx.x * blockDim.x + threadIdx.x;
    if (i < ep) {
        int p = atomicAdd(&g_pcur[pdst[i]], 1);
        g_pesrc[p] = psrc[i];
    } else {
        int j = i - ep;
        if (j < es) {
            int p = atomicAdd(&g_scur[sdst[j]], 1);
            g_sesrc[p] = ssrc[j];
        }
    }
}

// ---------------------------------------------------------------------------
// Phase 4: gather-sum, one warp per (dst row, edge set). Indices prefetched
// warp-wide (one coalesced load per 32 edges + shuffle) so the 4 row-loads
// per unrolled step have no index fetch in the dependence chain.
// Parent -> g_agg[d]; sibling -> out[d] = prop_z[d] + acc (fuses the copy).
__global__ void k_gather(const float* __restrict__ prop_z,
                         const float* __restrict__ mol_z,
                         float* __restrict__ out, int n_prop) {
    int gw = (blockIdx.x * blockDim.x + threadIdx.x) >> 5;
    int lane = threadIdx.x & 31;
    bool sib = gw >= n_prop;
    int d = sib ? gw - n_prop : gw;
    if (d >= n_prop) return;
    const int* off = sib ? g_soff : g_poff;
    const int* esrc = sib ? g_sesrc : g_pesrc;
    const float* src = sib ? mol_z : prop_z;

    int beg = off[d], end = off[d + 1];
    float4 acc = make_float4(0.f, 0.f, 0.f, 0.f);
    for (int base = beg; base < end; base += 32) {
        int cnt = end - base;
        if (cnt > 32) cnt = 32;
        int sidx = (lane < cnt) ? esrc[base + lane] : 0;
        int j = 0;
        for (; j + 4 <= cnt; j += 4) {
            int s0 = __shfl_sync(0xFFFFFFFFu, sidx, j);
            int s1 = __shfl_sync(0xFFFFFFFFu, sidx, j + 1);
            int s2 = __shfl_sync(0xFFFFFFFFu, sidx, j + 2);
            int s3 = __shfl_sync(0xFFFFFFFFu, sidx, j + 3);
            float4 a = __ldg(reinterpret_cast<const float4*>(src + (size_t)s0 * H) + lane);
            float4 b = __ldg(reinterpret_cast<const float4*>(src + (size_t)s1 * H) + lane);
            float4 c = __ldg(reinterpret_cast<const float4*>(src + (size_t)s2 * H) + lane);
            float4 f = __ldg(reinterpret_cast<const float4*>(src + (size_t)s3 * H) + lane);
            acc.x += (a.x + b.x) + (c.x + f.x);
            acc.y += (a.y + b.y) + (c.y + f.y);
            acc.z += (a.z + b.z) + (c.z + f.z);
            acc.w += (a.w + b.w) + (c.w + f.w);
        }
        for (; j < cnt; j++) {
            int s = __shfl_sync(0xFFFFFFFFu, sidx, j);
            float4 a = __ldg(reinterpret_cast<const float4*>(src + (size_t)s * H) + lane);
            acc.x += a.x; acc.y += a.y; acc.z += a.z; acc.w += a.w;
        }
    }

    if (sib) {
        float4 p = __ldg(reinterpret_cast<const float4*>(prop_z + (size_t)d * H) + lane);
        float4 v;
        v.x = p.x + acc.x; v.y = p.y + acc.y; v.z = p.z + acc.z; v.w = p.w + acc.w;
        reinterpret_cast<float4*>(out + (size_t)d * H)[lane] = v;
    } else {
        reinterpret_cast<float4*>(g_agg + (size_t)d * H)[lane] = acc;
    }
}

// ---------------------------------------------------------------------------
// Phase 5: out[r] += relu(g_agg[r] @ W^T + b), 8x8 register-tiled SGEMM.
// 128 threads = 16 col-groups x 8 row-groups; BM=64 rows/block, BK=32.
// As k-major with 65-word rows (conflict-free STS/LDS), Ws k-major 132-word
// rows (16B-aligned float4 reads).
__global__ void __launch_bounds__(128) k_gemm(const float* __restrict__ W,
                                              const float* __restrict__ bias,
                                              float* __restrict__ out, int n_prop) {
    __shared__ float As[BK][BM + 1];    // 32 x 65
    __shared__ float Ws[BK][H + 4];     // 32 x 132
    int tid = threadIdx.x;
    int cg = tid & 15;                  // columns cg*8 .. cg*8+7
    int rg = tid >> 4;                  // rows    rg*8 .. rg*8+7
    int row0 = blockIdx.x * BM;

    float acc[8][8];
#pragma unroll
    for (int i = 0; i < 8; i++)
#pragma unroll
        for (int j = 0; j < 8; j++) acc[i][j] = 0.f;

#pragma unroll 1
    for (int kt = 0; kt < H; kt += BK) {
        // A tile: 64 rows x 32 k (coalesced gmem, conflict-free STS)
#pragma unroll
        for (int idx = tid; idx < BM * BK; idx += 128) {
            int r = idx >> 5, kk = idx & 31;
            int rr = row0 + r;
            As[kk][r] = (rr < n_prop) ? g_agg[rr * H + kt + kk] : 0.f;
        }
        // W tile: 128 cols x 32 k
#pragma unroll
        for (int idx = tid; idx < H * BK; idx += 128) {
            int c = idx >> 5, kk = idx & 31;
            Ws[kk][c] = W[c * H + kt + kk];
        }
        __syncthreads();
#pragma unroll 8
        for (int k = 0; k < BK; k++) {
            float a[8], w[8];
#pragma unroll
            for (int i = 0; i < 8; i++) a[i] = As[k][rg * 8 + i];
            float4 w0 = *reinterpret_cast<const float4*>(&Ws[k][cg * 8]);
            float4 w1 = *reinterpret_cast<const float4*>(&Ws[k][cg * 8 + 4]);
            w[0] = w0.x; w[1] = w0.y; w[2] = w0.z; w[3] = w0.w;
            w[4] = w1.x; w[5] = w1.y; w[6] = w1.z; w[7] = w1.w;
#pragma unroll
            for (int i = 0; i < 8; i++)
#pragma unroll
                for (int j = 0; j < 8; j++)
                    acc[i][j] += a[i] * w[j];
        }
        __syncthreads();
    }

    float4 b0 = __ldg(reinterpret_cast<const float4*>(bias + cg * 8));
    float4 b1 = __ldg(reinterpret_cast<const float4*>(bias + cg * 8 + 4));
    float bb[8] = {b0.x, b0.y, b0.z, b0.w, b1.x, b1.y, b1.z, b1.w};

#pragma unroll
    for (int i = 0; i < 8; i++) {
        int rr = row0 + rg * 8 + i;
        if (rr < n_prop) {
            float4* o = reinterpret_cast<float4*>(out + (size_t)rr * H + cg * 8);
            float4 v0 = o[0], v1 = o[1];
            v0.x += fmaxf(acc[i][0] + bb[0], 0.f);
            v0.y += fmaxf(acc[i][1] + bb[1], 0.f);
            v0.z += fmaxf(acc[i][2] + bb[2], 0.f);
            v0.w += fmaxf(acc[i][3] + bb[3], 0.f);
            v1.x += fmaxf(acc[i][4] + bb[4], 0.f);
            v1.y += fmaxf(acc[i][5] + bb[5], 0.f);
            v1.z += fmaxf(acc[i][6] + bb[6], 0.f);
            v1.w += fmaxf(acc[i][7] + bb[7], 0.f);
            o[0] = v0; o[1] = v1;
        }
    }
}

extern "C" void kernel_launch(void* const* d_in, const int* in_sizes, int n_in,
                              void* d_out, int out_size) {
    const float* prop_z = (const float*)d_in[0];
    const float* mol_z  = (const float*)d_in[1];
    const float* W      = (const float*)d_in[2];
    const float* b      = (const float*)d_in[3];
    const int* psrc = (const int*)d_in[4];
    const int* pdst = (const int*)d_in[5];
    const int* ssrc = (const int*)d_in[6];
    const int* sdst = (const int*)d_in[7];

    int n_nodes = in_sizes[0] / H;
    int ep      = in_sizes[4];
    int es      = in_sizes[6];
    int n_prop  = in_sizes[8];
    float* out  = (float*)d_out;

    int ne = ep + es;
    int off4 = n_prop * (H / 4);
    int n4copy = (n_nodes - n_prop) * (H / 4);
    int pre_n = n4copy > ne ? n4copy : ne;
    k_pre<<<(pre_n + 255) / 256, 256>>>((const float4*)prop_z, (float4*)out,
                                        off4, n4copy, pdst, sdst, ep, es);

    k_scan<<<2, 1024>>>(n_prop);

    k_fill<<<(ne + 255) / 256, 256>>>(psrc, pdst, ssrc, sdst, ep, es);

    long long gt = (long long)2 * n_prop * 32;
    k_gather<<<(int)((gt + 255) / 256), 256>>>(prop_z, mol_z, out, n_prop);

    k_gemm<<<(n_prop + BM - 1) / BM, 128>>>(W, b, out, n_prop);
}